// round 2
// baseline (speedup 1.0000x reference)
#include <cuda_runtime.h>
#include <math.h>
#include <stdint.h>

#define C_CH 256
#define POOL 7
#define FEAT (POOL*POOL*C_CH)      /* 12544 */
#define R_MAX 1024
#define DCLS_MAX 80
#define M_MAX (R_MAX*DCLS_MAX)     /* 81920 */
#define NIMG_MAX 4
#define NHEAD_MAX 408
#define LOG_MAX_CONST 4.1351665567423556f

/* ------------------ scratch (static device globals, no allocation) ------------------ */
__device__ float  g_x0[(size_t)R_MAX*FEAT];     /* pooled features, 51.4 MB */
__device__ float  g_x1[(size_t)R_MAX*1024];
__device__ float  g_x2[(size_t)R_MAX*1024];
__device__ float  g_headout[(size_t)R_MAX*NHEAD_MAX];
__device__ float  g_Whead[(size_t)1024*NHEAD_MAX];
__device__ float  g_bhead[NHEAD_MAX];
__device__ float  g_cscore[M_MAX];
__device__ float4 g_cbox[M_MAX];
__device__ float  g_score_c[(size_t)NIMG_MAX*M_MAX];
__device__ float4 g_box_c[(size_t)NIMG_MAX*M_MAX];
__device__ float  g_area_c[(size_t)NIMG_MAX*M_MAX];
__device__ int    g_cls_c[(size_t)NIMG_MAX*M_MAX];
__device__ int    g_cnt[NIMG_MAX];

/* ------------------ ROI align: one block per proposal, 256 threads = channels ------- */
__global__ void roi_align_kernel(const float* __restrict__ prop,
                                 const int*   __restrict__ imidx,
                                 const float* __restrict__ f0, const float* __restrict__ f1,
                                 const float* __restrict__ f2, const float* __restrict__ f3,
                                 int H0, int H1, int H2, int H3)
{
    int r = blockIdx.x;
    __shared__ int   s_lvl, s_img, s_H;
    __shared__ int   s_y0[49], s_y1[49], s_x0[49], s_x1[49];
    __shared__ float s_wx[49], s_wy[49];

    if (threadIdx.x == 0) {
        float x1 = prop[r*4+0], y1 = prop[r*4+1], x2 = prop[r*4+2], y2 = prop[r*4+3];
        float pw = x2 - x1, ph = y2 - y1;
        float l = floorf(4.0f + log2f(sqrtf(pw*ph) / 224.0f + 1e-6f));
        l = fminf(fmaxf(l, 2.0f), 5.0f);
        int lvl = (int)l - 2;
        s_lvl = lvl;
        s_img = imidx[r];
        s_H   = (lvl==0 ? H0 : lvl==1 ? H1 : lvl==2 ? H2 : H3);
    }
    __syncthreads();
    int lvl = s_lvl, H = s_H;

    if (threadIdx.x < 49) {
        int py = threadIdx.x / 7, px = threadIdx.x % 7;
        float s  = 1.0f / (float)(4 << lvl);
        float x1 = prop[r*4+0]*s, y1 = prop[r*4+1]*s;
        float x2 = prop[r*4+2]*s, y2 = prop[r*4+3]*s;
        float gx = (px + 0.5f) / (float)POOL;
        float gy = (py + 0.5f) / (float)POOL;
        float xx = x1 + gx*(x2 - x1) - 0.5f;
        float yy = y1 + gy*(y2 - y1) - 0.5f;
        float x0f = floorf(xx), y0f = floorf(yy);
        s_wx[threadIdx.x] = xx - x0f;
        s_wy[threadIdx.x] = yy - y0f;
        int xi = (int)x0f, yi = (int)y0f;
        s_x0[threadIdx.x] = min(max(xi,     0), H-1);
        s_x1[threadIdx.x] = min(max(xi + 1, 0), H-1);
        s_y0[threadIdx.x] = min(max(yi,     0), H-1);
        s_y1[threadIdx.x] = min(max(yi + 1, 0), H-1);
    }
    __syncthreads();

    const float* fm = (lvl==0 ? f0 : lvl==1 ? f1 : lvl==2 ? f2 : f3);
    size_t imgBase = (size_t)s_img * H * H * C_CH;
    int c = threadIdx.x;
    float* out = &g_x0[(size_t)r * FEAT];

    for (int b = 0; b < 49; b++) {
        float wx = s_wx[b], wy = s_wy[b];
        size_t row0 = imgBase + (size_t)s_y0[b] * H * C_CH;
        size_t row1 = imgBase + (size_t)s_y1[b] * H * C_CH;
        size_t cx0  = (size_t)s_x0[b] * C_CH + c;
        size_t cx1  = (size_t)s_x1[b] * C_CH + c;
        float v00 = fm[row0 + cx0];
        float v01 = fm[row0 + cx1];
        float v10 = fm[row1 + cx0];
        float v11 = fm[row1 + cx1];
        float v = v00*(1.f-wx)*(1.f-wy) + v01*wx*(1.f-wy)
                + v10*(1.f-wx)*wy       + v11*wx*wy;
        out[b*C_CH + c] = v;
    }
}

/* ------------------ tf32x2 tensor-core GEMM ----------------------------------------- */
/* C[M,N] = A[M,K] * B[K,N] + bias, optional ReLU.                                      */
/* BM=128 BN=64 BK=16, 256 threads = 8 warps (4m x 2n), warp tile 32x32 (2x4 m16n8k8).  */
/* tf32 2-term split: hi*hi + hi*lo + lo*hi  (~2^-22 accuracy). Requires K % 16 == 0.   */

__device__ __forceinline__ void split_tf32(float v, uint32_t& hi, uint32_t& lo)
{
    uint32_t h; asm("cvt.rna.tf32.f32 %0, %1;" : "=r"(h) : "f"(v));
    float hf = __uint_as_float(h);
    uint32_t l; asm("cvt.rna.tf32.f32 %0, %1;" : "=r"(l) : "f"(v - hf));
    hi = h; lo = l;
}

#define MMA_TF32(d, a0, a1, a2, a3, b0, b1)                                   \
    asm volatile("mma.sync.aligned.m16n8k8.row.col.f32.tf32.tf32.f32 "        \
        "{%0,%1,%2,%3}, {%4,%5,%6,%7}, {%8,%9}, {%0,%1,%2,%3};"               \
        : "+f"(d[0]), "+f"(d[1]), "+f"(d[2]), "+f"(d[3])                      \
        : "r"(a0), "r"(a1), "r"(a2), "r"(a3), "r"(b0), "r"(b1))

__global__ __launch_bounds__(256) void gemm_tf32x2(
    const float* __restrict__ A, const float* __restrict__ B,
    const float* __restrict__ bias, float* __restrict__ C,
    int M, int N, int K, int relu)
{
    /* strides 132 / 68 are ≡ 4 (mod 16) -> conflict-free float2 fragment LDS */
    __shared__ float2 Aa[16][132];   /* [k][m] (hi,lo)  16.9 KB */
    __shared__ float2 Bb[16][68];    /* [k][n] (hi,lo)   8.7 KB */

    int tid  = threadIdx.x;
    int mBase = blockIdx.y * 128, nBase = blockIdx.x * 64;
    int lane = tid & 31, warp = tid >> 5;
    int wm = (warp & 3) * 32;        /* 4 warps along M */
    int wn = (warp >> 2) * 32;       /* 2 warps along N */
    int grp = lane >> 2, tig = lane & 3;

    float acc[2][4][4];
    #pragma unroll
    for (int i = 0; i < 2; i++)
        #pragma unroll
        for (int j = 0; j < 4; j++)
            #pragma unroll
            for (int q = 0; q < 4; q++) acc[i][j][q] = 0.f;

    /* global-load assignments */
    int arow = tid >> 1,  acol = (tid & 1) * 8;   /* A: 128 rows x 16 k, 8 floats/thread */
    int brow = tid >> 4,  bcol = (tid & 15) * 4;  /* B: 16 k x 64 n,    4 floats/thread */

    float areg[8], breg[4];
    bool aval = (mBase + arow) < M;

    auto loadGlobal = [&](int kt) {
        if (aval) {
            const float4* ap = reinterpret_cast<const float4*>(
                &A[(size_t)(mBase + arow) * K + kt + acol]);
            float4 v0 = ap[0], v1 = ap[1];
            areg[0]=v0.x; areg[1]=v0.y; areg[2]=v0.z; areg[3]=v0.w;
            areg[4]=v1.x; areg[5]=v1.y; areg[6]=v1.z; areg[7]=v1.w;
        } else {
            #pragma unroll
            for (int e = 0; e < 8; e++) areg[e] = 0.f;
        }
        const float* bp = &B[(size_t)(kt + brow) * N + nBase + bcol];
        #pragma unroll
        for (int e = 0; e < 4; e++)
            breg[e] = (nBase + bcol + e < N) ? bp[e] : 0.f;
    };
    auto storeSmem = [&]() {
        #pragma unroll
        for (int e = 0; e < 8; e++) {
            uint32_t hi, lo; split_tf32(areg[e], hi, lo);
            Aa[acol + e][arow] = make_float2(__uint_as_float(hi), __uint_as_float(lo));
        }
        #pragma unroll
        for (int e = 0; e < 4; e++) {
            uint32_t hi, lo; split_tf32(breg[e], hi, lo);
            Bb[brow][bcol + e] = make_float2(__uint_as_float(hi), __uint_as_float(lo));
        }
    };

    loadGlobal(0);
    storeSmem();
    __syncthreads();

    for (int kt = 16;; kt += 16) {
        bool more = kt < K;
        if (more) loadGlobal(kt);

        #pragma unroll
        for (int s = 0; s < 2; s++) {
            int k0 = s * 8;
            uint32_t ah[2][4], al[2][4];
            #pragma unroll
            for (int i = 0; i < 2; i++) {
                float2 q0 = Aa[k0 + tig    ][wm + i*16 + grp    ];
                float2 q1 = Aa[k0 + tig    ][wm + i*16 + grp + 8];
                float2 q2 = Aa[k0 + tig + 4][wm + i*16 + grp    ];
                float2 q3 = Aa[k0 + tig + 4][wm + i*16 + grp + 8];
                ah[i][0]=__float_as_uint(q0.x); al[i][0]=__float_as_uint(q0.y);
                ah[i][1]=__float_as_uint(q1.x); al[i][1]=__float_as_uint(q1.y);
                ah[i][2]=__float_as_uint(q2.x); al[i][2]=__float_as_uint(q2.y);
                ah[i][3]=__float_as_uint(q3.x); al[i][3]=__float_as_uint(q3.y);
            }
            uint32_t bh[4][2], bl[4][2];
            #pragma unroll
            for (int j = 0; j < 4; j++) {
                float2 p0 = Bb[k0 + tig    ][wn + j*8 + grp];
                float2 p1 = Bb[k0 + tig + 4][wn + j*8 + grp];
                bh[j][0]=__float_as_uint(p0.x); bl[j][0]=__float_as_uint(p0.y);
                bh[j][1]=__float_as_uint(p1.x); bl[j][1]=__float_as_uint(p1.y);
            }
            /* hi*hi, then hi*lo, then lo*hi — split-major order keeps the 8
               independent accumulators between reuses of the same acc */
            #pragma unroll
            for (int i = 0; i < 2; i++)
                #pragma unroll
                for (int j = 0; j < 4; j++)
                    MMA_TF32(acc[i][j], ah[i][0],ah[i][1],ah[i][2],ah[i][3], bh[j][0],bh[j][1]);
            #pragma unroll
            for (int i = 0; i < 2; i++)
                #pragma unroll
                for (int j = 0; j < 4; j++)
                    MMA_TF32(acc[i][j], ah[i][0],ah[i][1],ah[i][2],ah[i][3], bl[j][0],bl[j][1]);
            #pragma unroll
            for (int i = 0; i < 2; i++)
                #pragma unroll
                for (int j = 0; j < 4; j++)
                    MMA_TF32(acc[i][j], al[i][0],al[i][1],al[i][2],al[i][3], bh[j][0],bh[j][1]);
        }

        if (!more) break;
        __syncthreads();
        storeSmem();
        __syncthreads();
    }

    /* epilogue: bias + optional relu */
    #pragma unroll
    for (int i = 0; i < 2; i++) {
        int r0 = mBase + wm + i*16 + grp;
        int r1 = r0 + 8;
        #pragma unroll
        for (int j = 0; j < 4; j++) {
            int c0 = nBase + wn + j*8 + 2*tig;
            #pragma unroll
            for (int q = 0; q < 2; q++) {
                int col = c0 + q;
                if (col >= N) continue;
                float bv = bias[col];
                if (r0 < M) {
                    float v = acc[i][j][q] + bv;
                    if (relu) v = fmaxf(v, 0.f);
                    C[(size_t)r0 * N + col] = v;
                }
                if (r1 < M) {
                    float v = acc[i][j][2+q] + bv;
                    if (relu) v = fmaxf(v, 0.f);
                    C[(size_t)r1 * N + col] = v;
                }
            }
        }
    }
}

/* ------------------ pack class+reg heads into one weight matrix --------------------- */
__global__ void pack_heads_kernel(const float* __restrict__ Wc, const float* __restrict__ bc,
                                  const float* __restrict__ Wr, const float* __restrict__ br,
                                  int K, int NC, int NR)
{
    int NT = NC + NR;
    int total = K * NT;
    for (int idx = blockIdx.x * blockDim.x + threadIdx.x; idx < total;
         idx += gridDim.x * blockDim.x) {
        int row = idx / NT, col = idx % NT;
        g_Whead[(size_t)row * NT + col] =
            (col < NC) ? Wc[(size_t)row * NC + col] : Wr[(size_t)row * NR + (col - NC)];
    }
    if (blockIdx.x == 0 && threadIdx.x < NT)
        g_bhead[threadIdx.x] = (threadIdx.x < NC) ? bc[threadIdx.x] : br[threadIdx.x - NC];
}

/* ------------------ softmax + box decode: one block (128 thr) per proposal ---------- */
__global__ void decode_kernel(const float* __restrict__ prop,
                              const int*   __restrict__ imidx,
                              const float* __restrict__ imsizes,
                              const float* __restrict__ sthr_p,
                              const float* __restrict__ minsz_p,
                              int NC, int NT)
{
    int r = blockIdx.x;
    int t = threadIdx.x;
    __shared__ float sl[128];
    __shared__ float smax, ssum;

    const float* head = &g_headout[(size_t)r * NT];

    if (t < NC) sl[t] = head[t];
    __syncthreads();
    if (t == 0) { float m = sl[0]; for (int i = 1; i < NC; i++) m = fmaxf(m, sl[i]); smax = m; }
    __syncthreads();
    if (t < NC) sl[t] = expf(sl[t] - smax);
    __syncthreads();
    if (t == 0) { float s = 0.f; for (int i = 0; i < NC; i++) s += sl[i]; ssum = s; }
    __syncthreads();

    int D = NC - 1;
    if (t < D) {
        float score = sl[t+1] / ssum;
        float px1 = prop[r*4+0], py1 = prop[r*4+1];
        float px2 = prop[r*4+2], py2 = prop[r*4+3];
        float pw = px2 - px1, ph = py2 - py1;
        float cx = (px1 + px2)*0.5f, cy = (py1 + py2)*0.5f;
        const float* rg = &head[NC + (t+1)*4];
        float dx = rg[0]*0.1f, dy = rg[1]*0.1f;
        float dw = fminf(rg[2]*0.2f, LOG_MAX_CONST);
        float dh = fminf(rg[3]*0.2f, LOG_MAX_CONST);
        float ncx = dx*pw + cx, ncy = dy*ph + cy;
        float nw  = expf(dw)*pw, nh  = expf(dh)*ph;
        int im = imidx[r];
        float hb = imsizes[im*2+0], wb = imsizes[im*2+1];
        float bx1 = fminf(fmaxf(ncx - nw*0.5f, 0.f), wb);
        float bx2 = fminf(fmaxf(ncx + nw*0.5f, 0.f), wb);
        float by1 = fminf(fmaxf(ncy - nh*0.5f, 0.f), hb);
        float by2 = fminf(fmaxf(ncy + nh*0.5f, 0.f), hb);
        float sthr = *sthr_p, minsz = *minsz_p;
        bool valid = (score > sthr) && (bx2 - bx1 >= minsz) && (by2 - by1 >= minsz);
        int m = r*D + t;
        g_cscore[m] = valid ? score : -1.0f;
        g_cbox[m]   = make_float4(bx1, by1, bx2, by2);
    }
}

/* ------------------ deterministic (order-preserving) per-image compaction ----------- */
__global__ void compact_kernel(const int* __restrict__ imidx, int M, int D)
{
    int img  = blockIdx.x;
    int tid  = threadIdx.x;
    int lane = tid & 31, wid = tid >> 5;
    __shared__ int warpSum[32], warpOff[32];
    __shared__ int sBase, sTot;
    if (tid == 0) sBase = 0;
    __syncthreads();

    for (int start = 0; start < M; start += 1024) {
        int m = start + tid;
        bool f = false; float sc = 0.f;
        if (m < M) { sc = g_cscore[m]; f = (sc > 0.f) && (imidx[m / D] == img); }
        unsigned ball = __ballot_sync(0xffffffffu, f);
        int pre = __popc(ball & ((1u << lane) - 1u));
        if (lane == 0) warpSum[wid] = __popc(ball);
        __syncthreads();
        if (tid == 0) {
            int s = 0;
            for (int w = 0; w < 32; w++) { warpOff[w] = s; s += warpSum[w]; }
            sTot = s;
        }
        __syncthreads();
        if (f) {
            int k = sBase + warpOff[wid] + pre;
            size_t o = (size_t)img*M_MAX + k;
            float4 b = g_cbox[m];
            g_score_c[o] = sc;
            g_box_c[o]   = b;
            g_area_c[o]  = (b.z - b.x)*(b.w - b.y);
            g_cls_c[o]   = (m % D) + 1;
        }
        __syncthreads();
        if (tid == 0) sBase += sTot;
        __syncthreads();
    }
    if (tid == 0) g_cnt[img] = sBase;
}

/* ------------------ sequential NMS: one block per image ---------------------------- */
__global__ __launch_bounds__(1024) void nms_kernel(const float* __restrict__ iou_p,
                                                   float* __restrict__ out,
                                                   int n, int imtop)
{
    int img = blockIdx.x;
    int tid = threadIdx.x;
    int K = g_cnt[img];
    float iouT = *iou_p;
    float*  sc = &g_score_c[(size_t)img*M_MAX];
    float4* bx = &g_box_c[(size_t)img*M_MAX];
    float*  ar = &g_area_c[(size_t)img*M_MAX];
    int*    cl = &g_cls_c[(size_t)img*M_MAX];

    __shared__ float sval[1024];
    __shared__ int   sidx[1024];
    __shared__ float4 shb;  __shared__ float sha;  __shared__ int shc;

    float* oB = out + (size_t)img*imtop*4;
    float* oS = out + (size_t)n*imtop*4 + (size_t)img*imtop;
    float* oC = out + (size_t)n*imtop*5 + (size_t)img*imtop;

    for (int t = 0; t < imtop; t++) {
        /* argmax with first-index tie-break (matches jnp.argmax) */
        float best = -1e30f; int bi = 0x7fffffff;
        for (int k = tid; k < K; k += blockDim.x) {
            float v = sc[k];
            if (v > best || (v == best && k < bi)) { best = v; bi = k; }
        }
        sval[tid] = best; sidx[tid] = bi;
        __syncthreads();
        for (int s = blockDim.x >> 1; s > 0; s >>= 1) {
            if (tid < s) {
                float ov = sval[tid+s]; int oi = sidx[tid+s];
                if (ov > sval[tid] || (ov == sval[tid] && oi < sidx[tid])) {
                    sval[tid] = ov; sidx[tid] = oi;
                }
            }
            __syncthreads();
        }
        float wv = sval[0]; int wi = sidx[0];
        if (tid == 0 && wv > 0.f) { shb = bx[wi]; sha = ar[wi]; shc = cl[wi]; }
        __syncthreads();

        if (wv > 0.f) {
            float4 wb = shb; float wa = sha; int wc = shc;
            for (int k = tid; k < K; k += blockDim.x) {
                if (k == wi) { sc[k] = -1.f; continue; }
                if (cl[k] != wc) continue;  /* class-offset boxes never overlap cross-class */
                float4 b = bx[k];
                float iw = fmaxf(fminf(wb.z, b.z) - fmaxf(wb.x, b.x), 0.f);
                float ih = fmaxf(fminf(wb.w, b.w) - fmaxf(wb.y, b.y), 0.f);
                float inter = iw * ih;
                float iou = inter / (wa + ar[k] - inter + 1e-6f);
                if (iou > iouT) sc[k] = -1.f;
            }
            if (tid == 0) {
                oB[t*4+0] = wb.x; oB[t*4+1] = wb.y; oB[t*4+2] = wb.z; oB[t*4+3] = wb.w;
                oS[t] = wv;
                oC[t] = (float)wc;
            }
        } else {
            if (tid == 0) {
                oB[t*4+0] = 0.f; oB[t*4+1] = 0.f; oB[t*4+2] = 0.f; oB[t*4+3] = 0.f;
                oS[t] = 0.f;
                oC[t] = -1.f;
            }
        }
        __syncthreads();
    }
}

/* ------------------ host launch ---------------------------------------------------- */
extern "C" void kernel_launch(void* const* d_in, const int* in_sizes, int n_in,
                              void* d_out, int out_size)
{
    const float* prop    = (const float*)d_in[0];
    const int*   imidx   = (const int*)  d_in[1];
    const float* f0      = (const float*)d_in[2];
    const float* f1      = (const float*)d_in[3];
    const float* f2      = (const float*)d_in[4];
    const float* f3      = (const float*)d_in[5];
    const float* W0      = (const float*)d_in[6];
    const float* b0      = (const float*)d_in[7];
    const float* W1      = (const float*)d_in[8];
    const float* b1      = (const float*)d_in[9];
    const float* Wc      = (const float*)d_in[10];
    const float* bc      = (const float*)d_in[11];
    const float* Wr      = (const float*)d_in[12];
    const float* br      = (const float*)d_in[13];
    const float* imsizes = (const float*)d_in[14];
    const float* sthr    = (const float*)d_in[15];
    const float* iouthr  = (const float*)d_in[16];
    /* d_in[17] = imtop (derived from out_size instead) */
    const float* minsz   = (const float*)d_in[18];

    int R  = in_sizes[0] / 4;
    int n  = in_sizes[14] / 2;
    int imtop = out_size / (6 * n);
    int N0 = in_sizes[7];    /* 1024 */
    int N1 = in_sizes[9];    /* 1024 */
    int NC = in_sizes[11];   /* 81  */
    int NR = in_sizes[13];   /* 324 */
    int NT = NC + NR;        /* 405 */
    int D  = NC - 1;
    int M  = R * D;

    int H0 = (int)(sqrt((double)in_sizes[2] / ((double)n * C_CH)) + 0.5);
    int H1 = (int)(sqrt((double)in_sizes[3] / ((double)n * C_CH)) + 0.5);
    int H2 = (int)(sqrt((double)in_sizes[4] / ((double)n * C_CH)) + 0.5);
    int H3 = (int)(sqrt((double)in_sizes[5] / ((double)n * C_CH)) + 0.5);

    float *px0, *px1, *px2, *phead, *pWh, *pbh;
    cudaGetSymbolAddress((void**)&px0,   g_x0);
    cudaGetSymbolAddress((void**)&px1,   g_x1);
    cudaGetSymbolAddress((void**)&px2,   g_x2);
    cudaGetSymbolAddress((void**)&phead, g_headout);
    cudaGetSymbolAddress((void**)&pWh,   g_Whead);
    cudaGetSymbolAddress((void**)&pbh,   g_bhead);

    /* 1. ROI align -> pooled features; pack head weights concurrently */
    roi_align_kernel<<<R, 256>>>(prop, imidx, f0, f1, f2, f3, H0, H1, H2, H3);
    pack_heads_kernel<<<256, 512>>>(Wc, bc, Wr, br, N1, NC, NR);

    /* 2. FC1 (FEAT->N0) + ReLU */
    {
        dim3 g((N0 + 63)/64, (R + 127)/128);
        gemm_tf32x2<<<g, 256>>>(px0, W0, b0, px1, R, N0, FEAT, 1);
    }
    /* 3. FC2 (N0->N1) + ReLU */
    {
        dim3 g((N1 + 63)/64, (R + 127)/128);
        gemm_tf32x2<<<g, 256>>>(px1, W1, b1, px2, R, N1, N0, 1);
    }
    /* 4. fused class+reg head (N1->NT) */
    {
        dim3 g((NT + 63)/64, (R + 127)/128);
        gemm_tf32x2<<<g, 256>>>(px2, pWh, pbh, phead, R, NT, N1, 0);
    }
    /* 5. softmax + box decode */
    decode_kernel<<<R, 128>>>(prop, imidx, imsizes, sthr, minsz, NC, NT);

    /* 6. deterministic per-image compaction */
    compact_kernel<<<n, 1024>>>(imidx, M, D);

    /* 7. sequential NMS + output write */
    nms_kernel<<<n, 1024>>>(iouthr, (float*)d_out, n, imtop);
}

// round 4
// speedup vs baseline: 2.8443x; 2.8443x over previous
#include <cuda_runtime.h>
#include <cuda_fp16.h>
#include <math.h>
#include <stdint.h>

#define C_CH 256
#define POOL 7
#define FEAT (POOL*POOL*C_CH)      /* 12544 */
#define R_MAX 1024
#define DCLS_MAX 80
#define M_MAX (R_MAX*DCLS_MAX)     /* 81920 */
#define NIMG_MAX 4
#define NHEAD_MAX 408
#define LOG_MAX_CONST 4.1351665567423556f

/* ------------------ scratch (static device globals, no allocation) ------------------ */
__device__ __half g_x0h[(size_t)R_MAX*FEAT];    /* pooled features hi, 25.7 MB */
__device__ __half g_x0l[(size_t)R_MAX*FEAT];    /* pooled features lo */
__device__ __half g_W0th[(size_t)1024*FEAT];    /* W0^T hi  [N=1024][K=12544] */
__device__ __half g_W0tl[(size_t)1024*FEAT];
__device__ __half g_W1th[(size_t)1024*1024];
__device__ __half g_W1tl[(size_t)1024*1024];
__device__ __half g_Whth[(size_t)NHEAD_MAX*1024];
__device__ __half g_Whtl[(size_t)NHEAD_MAX*1024];
__device__ __half g_x1h[(size_t)R_MAX*1024];
__device__ __half g_x1l[(size_t)R_MAX*1024];
__device__ __half g_x2h[(size_t)R_MAX*1024];
__device__ __half g_x2l[(size_t)R_MAX*1024];
__device__ float  g_headout[(size_t)R_MAX*NHEAD_MAX];
__device__ float  g_bhead[NHEAD_MAX];
__device__ float  g_cscore[M_MAX];
__device__ float4 g_cbox[M_MAX];
__device__ float  g_score_c[(size_t)NIMG_MAX*M_MAX];
__device__ float4 g_box_c[(size_t)NIMG_MAX*M_MAX];
__device__ float  g_area_c[(size_t)NIMG_MAX*M_MAX];
__device__ int    g_cls_c[(size_t)NIMG_MAX*M_MAX];
__device__ int    g_cnt[NIMG_MAX];

/* ------------------ helpers --------------------------------------------------------- */
__device__ __forceinline__ uint32_t smem_u32(const void* p) {
    uint32_t a;
    asm("{ .reg .u64 t; cvta.to.shared.u64 t, %1; cvt.u32.u64 %0, t; }" : "=r"(a) : "l"(p));
    return a;
}
__device__ __forceinline__ void split_h(float v, __half& hi, __half& lo)
{
    hi = __float2half_rn(v);
    lo = __float2half_rn(v - __half2float(hi));
}

#define LDSM4(r0,r1,r2,r3, addr) \
    asm volatile("ldmatrix.sync.aligned.m8n8.x4.shared.b16 {%0,%1,%2,%3}, [%4];" \
        : "=r"(r0),"=r"(r1),"=r"(r2),"=r"(r3) : "r"(addr))

#define MMA16816(d, a, b) \
    asm volatile("mma.sync.aligned.m16n8k16.row.col.f32.f16.f16.f32 " \
        "{%0,%1,%2,%3}, {%4,%5,%6,%7}, {%8,%9}, {%0,%1,%2,%3};" \
        : "+f"((d)[0]), "+f"((d)[1]), "+f"((d)[2]), "+f"((d)[3]) \
        : "r"((a)[0]), "r"((a)[1]), "r"((a)[2]), "r"((a)[3]), "r"((b)[0]), "r"((b)[1]))

#define CPASYNC16(dst, src, sz) \
    asm volatile("cp.async.ca.shared.global [%0], [%1], 16, %2;" \
        :: "r"(dst), "l"(src), "r"(sz))

/* ------------------ ROI align: one block per proposal, 256 threads = channels ------- */
__global__ void roi_align_kernel(const float* __restrict__ prop,
                                 const int*   __restrict__ imidx,
                                 const float* __restrict__ f0, const float* __restrict__ f1,
                                 const float* __restrict__ f2, const float* __restrict__ f3,
                                 int H0, int H1, int H2, int H3)
{
    int r = blockIdx.x;
    __shared__ int   s_lvl, s_img, s_H;
    __shared__ int   s_y0[49], s_y1[49], s_x0[49], s_x1[49];
    __shared__ float s_wx[49], s_wy[49];

    if (threadIdx.x == 0) {
        float x1 = prop[r*4+0], y1 = prop[r*4+1], x2 = prop[r*4+2], y2 = prop[r*4+3];
        float pw = x2 - x1, ph = y2 - y1;
        float l = floorf(4.0f + log2f(sqrtf(pw*ph) / 224.0f + 1e-6f));
        l = fminf(fmaxf(l, 2.0f), 5.0f);
        int lvl = (int)l - 2;
        s_lvl = lvl;
        s_img = imidx[r];
        s_H   = (lvl==0 ? H0 : lvl==1 ? H1 : lvl==2 ? H2 : H3);
    }
    __syncthreads();
    int lvl = s_lvl, H = s_H;

    if (threadIdx.x < 49) {
        int py = threadIdx.x / 7, px = threadIdx.x % 7;
        float s  = 1.0f / (float)(4 << lvl);
        float x1 = prop[r*4+0]*s, y1 = prop[r*4+1]*s;
        float x2 = prop[r*4+2]*s, y2 = prop[r*4+3]*s;
        float gx = (px + 0.5f) / (float)POOL;
        float gy = (py + 0.5f) / (float)POOL;
        float xx = x1 + gx*(x2 - x1) - 0.5f;
        float yy = y1 + gy*(y2 - y1) - 0.5f;
        float x0f = floorf(xx), y0f = floorf(yy);
        s_wx[threadIdx.x] = xx - x0f;
        s_wy[threadIdx.x] = yy - y0f;
        int xi = (int)x0f, yi = (int)y0f;
        s_x0[threadIdx.x] = min(max(xi,     0), H-1);
        s_x1[threadIdx.x] = min(max(xi + 1, 0), H-1);
        s_y0[threadIdx.x] = min(max(yi,     0), H-1);
        s_y1[threadIdx.x] = min(max(yi + 1, 0), H-1);
    }
    __syncthreads();

    const float* fm = (lvl==0 ? f0 : lvl==1 ? f1 : lvl==2 ? f2 : f3);
    size_t imgBase = (size_t)s_img * H * H * C_CH;
    int c = threadIdx.x;
    size_t outBase = (size_t)r * FEAT;

    for (int b = 0; b < 49; b++) {
        float wx = s_wx[b], wy = s_wy[b];
        size_t row0 = imgBase + (size_t)s_y0[b] * H * C_CH;
        size_t row1 = imgBase + (size_t)s_y1[b] * H * C_CH;
        size_t cx0  = (size_t)s_x0[b] * C_CH + c;
        size_t cx1  = (size_t)s_x1[b] * C_CH + c;
        float v00 = fm[row0 + cx0];
        float v01 = fm[row0 + cx1];
        float v10 = fm[row1 + cx0];
        float v11 = fm[row1 + cx1];
        float v = v00*(1.f-wx)*(1.f-wy) + v01*wx*(1.f-wy)
                + v10*(1.f-wx)*wy       + v11*wx*wy;
        __half h, l; split_h(v, h, l);
        g_x0h[outBase + b*C_CH + c] = h;
        g_x0l[outBase + b*C_CH + c] = l;
    }
}

/* ------------------ transpose + fp16 split: in fp32 [K][N] -> out [roff+n][Kout] ---- */
__global__ void tsplit_kernel(const float* __restrict__ in, int K, int N,
                              __half* __restrict__ outH, __half* __restrict__ outL,
                              int roff, int Kout)
{
    __shared__ float tile[32][33];
    int k0 = blockIdx.y * 32, n0 = blockIdx.x * 32;
    int tx = threadIdx.x, ty = threadIdx.y;   /* (32, 8) */
    #pragma unroll
    for (int j = 0; j < 4; j++) {
        int k = k0 + ty + j*8, n = n0 + tx;
        tile[ty + j*8][tx] = (k < K && n < N) ? in[(size_t)k * N + n] : 0.f;
    }
    __syncthreads();
    #pragma unroll
    for (int j = 0; j < 4; j++) {
        int n = n0 + ty + j*8, k = k0 + tx;
        if (n < N && k < Kout) {
            __half h, l; split_h(tile[tx][ty + j*8], h, l);
            size_t o = (size_t)(roff + n) * Kout + k;
            outH[o] = h;
            outL[o] = l;
        }
    }
}

__global__ void pack_bias_kernel(const float* __restrict__ bc, const float* __restrict__ br,
                                 int NC, int NR)
{
    int t = threadIdx.x;
    if (t < NC + NR)
        g_bhead[t] = (t < NC) ? bc[t] : br[t - NC];
}

/* ------------------ fp16x2 tensor-core GEMM ----------------------------------------- */
/* C[M,N] = A[M,K] * Bt[N,K]^T + bias.  A,Bt pre-split hi/lo fp16, both K-major.        */
/* 3 HMMA passes: hh + hl + lh  (~2^-22 accuracy, same as tf32 3-pass).                 */
/* CTA tile 128x64, BK=32, 256 threads (8 warps, 32x32 warp tiles), cp.async 2-stage.   */
/* Requires K % 32 == 0.                                                                */

#define SA 40                       /* smem row stride in fp16 (80B: conflict-free)     */
#define AH_B 0
#define AL_B 10240
#define BH_B 20480
#define BL_B 25600
#define GSTG 30720
#define GT_DSMEM (2*GSTG)

__global__ __launch_bounds__(256) void gemm_h2(
    const __half* __restrict__ Ah, const __half* __restrict__ Al,
    const __half* __restrict__ Bh, const __half* __restrict__ Bl,
    const float* __restrict__ bias,
    float* __restrict__ Cf, __half* __restrict__ Ch, __half* __restrict__ Cl,
    int M, int N, int K, int mode /* 0: fp32 out, 1: split fp16 out + relu */)
{
    extern __shared__ __align__(16) char sm[];
    uint32_t smb = smem_u32(sm);

    int tid = threadIdx.x, lane = tid & 31, warp = tid >> 5;
    int mBase = blockIdx.y * 128, nBase = blockIdx.x * 64;
    int wm = (warp & 3) * 32, wn = (warp >> 2) * 32;

    float acc[2][4][4];
    #pragma unroll
    for (int i = 0; i < 2; i++)
        #pragma unroll
        for (int j = 0; j < 4; j++)
            #pragma unroll
            for (int q = 0; q < 4; q++) acc[i][j][q] = 0.f;

    int tiles = K >> 5;

    auto loadTile = [&](int t) {
        int kt = t << 5;
        uint32_t base = smb + (t & 1) * GSTG;
        #pragma unroll
        for (int i = 0; i < 2; i++) {
            int ch = tid + i*256;
            int row = ch >> 2, kc = (ch & 3) << 3;
            size_t gi = (size_t)(mBase + row) * K + kt + kc;
            uint32_t d = base + (uint32_t)(row*SA + kc)*2;
            int sz = (mBase + row < M) ? 16 : 0;
            CPASYNC16(d + AH_B, Ah + gi, sz);
            CPASYNC16(d + AL_B, Al + gi, sz);
        }
        {
            int row = tid >> 2, kc = (tid & 3) << 3;
            size_t gi = (size_t)(nBase + row) * K + kt + kc;
            uint32_t d = base + (uint32_t)(row*SA + kc)*2;
            int sz = (nBase + row < N) ? 16 : 0;
            CPASYNC16(d + BH_B, Bh + gi, sz);
            CPASYNC16(d + BL_B, Bl + gi, sz);
        }
        asm volatile("cp.async.commit_group;");
    };

    loadTile(0);
    if (tiles > 1) loadTile(1); else asm volatile("cp.async.commit_group;");

    int lm = lane >> 3, lr = lane & 7;
    /* A frag addr: row = wm + mi*16 + (lm&1)*8 + lr, col = k + (lm>>1)*8 */
    uint32_t aoff0 = (uint32_t)((wm + (lm&1)*8 + lr)*SA + (lm>>1)*8) * 2;
    /* B frag addr: row = wn + g*16 + (lm>>1)*8 + lr, col = k + (lm&1)*8 */
    uint32_t boff0 = (uint32_t)((wn + (lm>>1)*8 + lr)*SA + (lm&1)*8) * 2;

    for (int t = 0; t < tiles; t++) {
        asm volatile("cp.async.wait_group 1;");
        __syncthreads();
        uint32_t base = smb + (t & 1) * GSTG;

        #pragma unroll
        for (int ks = 0; ks < 2; ks++) {
            uint32_t kb = (uint32_t)(ks * 16) * 2;
            uint32_t ah[2][4], al[2][4];
            #pragma unroll
            for (int mi = 0; mi < 2; mi++) {
                uint32_t off = aoff0 + (uint32_t)(mi*16*SA)*2 + kb;
                LDSM4(ah[mi][0], ah[mi][1], ah[mi][2], ah[mi][3], base + AH_B + off);
                LDSM4(al[mi][0], al[mi][1], al[mi][2], al[mi][3], base + AL_B + off);
            }
            uint32_t bh[4][2], bl[4][2];
            #pragma unroll
            for (int g = 0; g < 2; g++) {
                uint32_t off = boff0 + (uint32_t)(g*16*SA)*2 + kb;
                uint32_t r0, r1, r2, r3;
                LDSM4(r0, r1, r2, r3, base + BH_B + off);
                bh[g*2][0]=r0; bh[g*2][1]=r1; bh[g*2+1][0]=r2; bh[g*2+1][1]=r3;
                LDSM4(r0, r1, r2, r3, base + BL_B + off);
                bl[g*2][0]=r0; bl[g*2][1]=r1; bl[g*2+1][0]=r2; bl[g*2+1][1]=r3;
            }
            #pragma unroll
            for (int mi = 0; mi < 2; mi++)
                #pragma unroll
                for (int nj = 0; nj < 4; nj++)
                    MMA16816(acc[mi][nj], ah[mi], bh[nj]);
            #pragma unroll
            for (int mi = 0; mi < 2; mi++)
                #pragma unroll
                for (int nj = 0; nj < 4; nj++)
                    MMA16816(acc[mi][nj], ah[mi], bl[nj]);
            #pragma unroll
            for (int mi = 0; mi < 2; mi++)
                #pragma unroll
                for (int nj = 0; nj < 4; nj++)
                    MMA16816(acc[mi][nj], al[mi], bh[nj]);
        }

        __syncthreads();
        if (t + 2 < tiles) loadTile(t + 2);
        else asm volatile("cp.async.commit_group;");
    }

    /* epilogue */
    #pragma unroll
    for (int mi = 0; mi < 2; mi++) {
        #pragma unroll
        for (int nj = 0; nj < 4; nj++) {
            #pragma unroll
            for (int q = 0; q < 4; q++) {
                int row = mBase + wm + mi*16 + (lane >> 2) + (q >> 1)*8;
                int col = nBase + wn + nj*8 + ((lane & 3) << 1) + (q & 1);
                if (row < M && col < N) {
                    float v = acc[mi][nj][q] + bias[col];
                    if (mode == 1) {
                        v = fmaxf(v, 0.f);
                        __half h, l; split_h(v, h, l);
                        Ch[(size_t)row * N + col] = h;
                        Cl[(size_t)row * N + col] = l;
                    } else {
                        Cf[(size_t)row * N + col] = v;
                    }
                }
            }
        }
    }
}

/* ------------------ softmax + box decode: one block (128 thr) per proposal ---------- */
__global__ void decode_kernel(const float* __restrict__ prop,
                              const int*   __restrict__ imidx,
                              const float* __restrict__ imsizes,
                              const float* __restrict__ sthr_p,
                              const float* __restrict__ minsz_p,
                              int NC, int NT)
{
    int r = blockIdx.x;
    int t = threadIdx.x;
    __shared__ float sl[128];
    __shared__ float smax, ssum;

    const float* head = &g_headout[(size_t)r * NT];

    if (t < NC) sl[t] = head[t];
    __syncthreads();
    if (t == 0) { float m = sl[0]; for (int i = 1; i < NC; i++) m = fmaxf(m, sl[i]); smax = m; }
    __syncthreads();
    if (t < NC) sl[t] = expf(sl[t] - smax);
    __syncthreads();
    if (t == 0) { float s = 0.f; for (int i = 0; i < NC; i++) s += sl[i]; ssum = s; }
    __syncthreads();

    int D = NC - 1;
    if (t < D) {
        float score = sl[t+1] / ssum;
        float px1 = prop[r*4+0], py1 = prop[r*4+1];
        float px2 = prop[r*4+2], py2 = prop[r*4+3];
        float pw = px2 - px1, ph = py2 - py1;
        float cx = (px1 + px2)*0.5f, cy = (py1 + py2)*0.5f;
        const float* rg = &head[NC + (t+1)*4];
        float dx = rg[0]*0.1f, dy = rg[1]*0.1f;
        float dw = fminf(rg[2]*0.2f, LOG_MAX_CONST);
        float dh = fminf(rg[3]*0.2f, LOG_MAX_CONST);
        float ncx = dx*pw + cx, ncy = dy*ph + cy;
        float nw  = expf(dw)*pw, nh  = expf(dh)*ph;
        int im = imidx[r];
        float hb = imsizes[im*2+0], wb = imsizes[im*2+1];
        float bx1 = fminf(fmaxf(ncx - nw*0.5f, 0.f), wb);
        float bx2 = fminf(fmaxf(ncx + nw*0.5f, 0.f), wb);
        float by1 = fminf(fmaxf(ncy - nh*0.5f, 0.f), hb);
        float by2 = fminf(fmaxf(ncy + nh*0.5f, 0.f), hb);
        float sthr = *sthr_p, minsz = *minsz_p;
        bool valid = (score > sthr) && (bx2 - bx1 >= minsz) && (by2 - by1 >= minsz);
        int m = r*D + t;
        g_cscore[m] = valid ? score : -1.0f;
        g_cbox[m]   = make_float4(bx1, by1, bx2, by2);
    }
}

/* ------------------ deterministic (order-preserving) per-image compaction ----------- */
__global__ void compact_kernel(const int* __restrict__ imidx, int M, int D)
{
    int img  = blockIdx.x;
    int tid  = threadIdx.x;
    int lane = tid & 31, wid = tid >> 5;
    __shared__ int warpSum[32], warpOff[32];
    __shared__ int sBase, sTot;
    if (tid == 0) sBase = 0;
    __syncthreads();

    for (int start = 0; start < M; start += 1024) {
        int m = start + tid;
        bool f = false; float sc = 0.f;
        if (m < M) { sc = g_cscore[m]; f = (sc > 0.f) && (imidx[m / D] == img); }
        unsigned ball = __ballot_sync(0xffffffffu, f);
        int pre = __popc(ball & ((1u << lane) - 1u));
        if (lane == 0) warpSum[wid] = __popc(ball);
        __syncthreads();
        if (tid == 0) {
            int s = 0;
            for (int w = 0; w < 32; w++) { warpOff[w] = s; s += warpSum[w]; }
            sTot = s;
        }
        __syncthreads();
        if (f) {
            int k = sBase + warpOff[wid] + pre;
            size_t o = (size_t)img*M_MAX + k;
            float4 b = g_cbox[m];
            g_score_c[o] = sc;
            g_box_c[o]   = b;
            g_area_c[o]  = (b.z - b.x)*(b.w - b.y);
            g_cls_c[o]   = (m % D) + 1;
        }
        __syncthreads();
        if (tid == 0) sBase += sTot;
        __syncthreads();
    }
    if (tid == 0) g_cnt[img] = sBase;
}

/* ------------------ sequential NMS: one block per image ---------------------------- */
__global__ __launch_bounds__(1024) void nms_kernel(const float* __restrict__ iou_p,
                                                   float* __restrict__ out,
                                                   int n, int imtop)
{
    int img = blockIdx.x;
    int tid = threadIdx.x;
    int K = g_cnt[img];
    float iouT = *iou_p;
    float*  sc = &g_score_c[(size_t)img*M_MAX];
    float4* bx = &g_box_c[(size_t)img*M_MAX];
    float*  ar = &g_area_c[(size_t)img*M_MAX];
    int*    cl = &g_cls_c[(size_t)img*M_MAX];

    __shared__ float sval[1024];
    __shared__ int   sidx[1024];
    __shared__ float4 shb;  __shared__ float sha;  __shared__ int shc;

    float* oB = out + (size_t)img*imtop*4;
    float* oS = out + (size_t)n*imtop*4 + (size_t)img*imtop;
    float* oC = out + (size_t)n*imtop*5 + (size_t)img*imtop;

    for (int t = 0; t < imtop; t++) {
        float best = -1e30f; int bi = 0x7fffffff;
        for (int k = tid; k < K; k += blockDim.x) {
            float v = sc[k];
            if (v > best || (v == best && k < bi)) { best = v; bi = k; }
        }
        sval[tid] = best; sidx[tid] = bi;
        __syncthreads();
        for (int s = blockDim.x >> 1; s > 0; s >>= 1) {
            if (tid < s) {
                float ov = sval[tid+s]; int oi = sidx[tid+s];
                if (ov > sval[tid] || (ov == sval[tid] && oi < sidx[tid])) {
                    sval[tid] = ov; sidx[tid] = oi;
                }
            }
            __syncthreads();
        }
        float wv = sval[0]; int wi = sidx[0];
        if (tid == 0 && wv > 0.f) { shb = bx[wi]; sha = ar[wi]; shc = cl[wi]; }
        __syncthreads();

        if (wv > 0.f) {
            float4 wb = shb; float wa = sha; int wc = shc;
            for (int k = tid; k < K; k += blockDim.x) {
                if (k == wi) { sc[k] = -1.f; continue; }
                if (cl[k] != wc) continue;
                float4 b = bx[k];
                float iw = fmaxf(fminf(wb.z, b.z) - fmaxf(wb.x, b.x), 0.f);
                float ih = fmaxf(fminf(wb.w, b.w) - fmaxf(wb.y, b.y), 0.f);
                float inter = iw * ih;
                float iou = inter / (wa + ar[k] - inter + 1e-6f);
                if (iou > iouT) sc[k] = -1.f;
            }
            if (tid == 0) {
                oB[t*4+0] = wb.x; oB[t*4+1] = wb.y; oB[t*4+2] = wb.z; oB[t*4+3] = wb.w;
                oS[t] = wv;
                oC[t] = (float)wc;
            }
        } else {
            if (tid == 0) {
                oB[t*4+0] = 0.f; oB[t*4+1] = 0.f; oB[t*4+2] = 0.f; oB[t*4+3] = 0.f;
                oS[t] = 0.f;
                oC[t] = -1.f;
            }
        }
        __syncthreads();
    }
}

/* ------------------ host launch ---------------------------------------------------- */
extern "C" void kernel_launch(void* const* d_in, const int* in_sizes, int n_in,
                              void* d_out, int out_size)
{
    const float* prop    = (const float*)d_in[0];
    const int*   imidx   = (const int*)  d_in[1];
    const float* f0      = (const float*)d_in[2];
    const float* f1      = (const float*)d_in[3];
    const float* f2      = (const float*)d_in[4];
    const float* f3      = (const float*)d_in[5];
    const float* W0      = (const float*)d_in[6];
    const float* b0      = (const float*)d_in[7];
    const float* W1      = (const float*)d_in[8];
    const float* b1      = (const float*)d_in[9];
    const float* Wc      = (const float*)d_in[10];
    const float* bc      = (const float*)d_in[11];
    const float* Wr      = (const float*)d_in[12];
    const float* br      = (const float*)d_in[13];
    const float* imsizes = (const float*)d_in[14];
    const float* sthr    = (const float*)d_in[15];
    const float* iouthr  = (const float*)d_in[16];
    const float* minsz   = (const float*)d_in[18];

    int R  = in_sizes[0] / 4;
    int n  = in_sizes[14] / 2;
    int imtop = out_size / (6 * n);
    int N0 = in_sizes[7];    /* 1024 */
    int N1 = in_sizes[9];    /* 1024 */
    int NC = in_sizes[11];   /* 81  */
    int NR = in_sizes[13];   /* 324 */
    int NT = NC + NR;        /* 405 */
    int D  = NC - 1;
    int M  = R * D;

    int H0 = (int)(sqrt((double)in_sizes[2] / ((double)n * C_CH)) + 0.5);
    int H1 = (int)(sqrt((double)in_sizes[3] / ((double)n * C_CH)) + 0.5);
    int H2 = (int)(sqrt((double)in_sizes[4] / ((double)n * C_CH)) + 0.5);
    int H3 = (int)(sqrt((double)in_sizes[5] / ((double)n * C_CH)) + 0.5);

    __half *px0h, *px0l, *pW0h, *pW0l, *pW1h, *pW1l, *pWhh, *pWhl;
    __half *px1h, *px1l, *px2h, *px2l;
    float *phead, *pbh;
    cudaGetSymbolAddress((void**)&px0h, g_x0h);  cudaGetSymbolAddress((void**)&px0l, g_x0l);
    cudaGetSymbolAddress((void**)&pW0h, g_W0th); cudaGetSymbolAddress((void**)&pW0l, g_W0tl);
    cudaGetSymbolAddress((void**)&pW1h, g_W1th); cudaGetSymbolAddress((void**)&pW1l, g_W1tl);
    cudaGetSymbolAddress((void**)&pWhh, g_Whth); cudaGetSymbolAddress((void**)&pWhl, g_Whtl);
    cudaGetSymbolAddress((void**)&px1h, g_x1h);  cudaGetSymbolAddress((void**)&px1l, g_x1l);
    cudaGetSymbolAddress((void**)&px2h, g_x2h);  cudaGetSymbolAddress((void**)&px2l, g_x2l);
    cudaGetSymbolAddress((void**)&phead, g_headout);
    cudaGetSymbolAddress((void**)&pbh,   g_bhead);

    cudaFuncSetAttribute(gemm_h2, cudaFuncAttributeMaxDynamicSharedMemorySize, GT_DSMEM);

    /* 1. ROI align -> split pooled features; weight transpose+split */
    roi_align_kernel<<<R, 256>>>(prop, imidx, f0, f1, f2, f3, H0, H1, H2, H3);
    {
        dim3 b(32, 8);
        tsplit_kernel<<<dim3((N0+31)/32, (FEAT+31)/32), b>>>(W0, FEAT, N0, pW0h, pW0l, 0, FEAT);
        tsplit_kernel<<<dim3((N1+31)/32, (N0+31)/32),  b>>>(W1, N0, N1, pW1h, pW1l, 0, N0);
        tsplit_kernel<<<dim3((NC+31)/32, (N1+31)/32),  b>>>(Wc, N1, NC, pWhh, pWhl, 0, N1);
        tsplit_kernel<<<dim3((NR+31)/32, (N1+31)/32),  b>>>(Wr, N1, NR, pWhh, pWhl, NC, N1);
        pack_bias_kernel<<<1, 512>>>(bc, br, NC, NR);
    }

    /* 2. FC1 (FEAT->N0) + ReLU, split fp16 out */
    {
        dim3 g((N0 + 63)/64, (R + 127)/128);
        gemm_h2<<<g, 256, GT_DSMEM>>>(px0h, px0l, pW0h, pW0l, b0,
                                      nullptr, px1h, px1l, R, N0, FEAT, 1);
    }
    /* 3. FC2 (N0->N1) + ReLU, split fp16 out */
    {
        dim3 g((N1 + 63)/64, (R + 127)/128);
        gemm_h2<<<g, 256, GT_DSMEM>>>(px1h, px1l, pW1h, pW1l, b1,
                                      nullptr, px2h, px2l, R, N1, N0, 1);
    }
    /* 4. fused class+reg head (N1->NT), fp32 out */
    {
        dim3 g((NT + 63)/64, (R + 127)/128);
        gemm_h2<<<g, 256, GT_DSMEM>>>(px2h, px2l, pWhh, pWhl, pbh,
                                      phead, nullptr, nullptr, R, NT, N1, 0);
    }
    /* 5. softmax + box decode */
    decode_kernel<<<R, 128>>>(prop, imidx, imsizes, sthr, minsz, NC, NT);

    /* 6. deterministic per-image compaction */
    compact_kernel<<<n, 1024>>>(imidx, M, D);

    /* 7. sequential NMS + output write */
    nms_kernel<<<n, 1024>>>(iouthr, (float*)d_out, n, imtop);
}

// round 5
// speedup vs baseline: 4.6343x; 1.6293x over previous
#include <cuda_runtime.h>
#include <cuda_fp16.h>
#include <math.h>
#include <stdint.h>

#define C_CH 256
#define POOL 7
#define FEAT (POOL*POOL*C_CH)      /* 12544 */
#define R_MAX 1024
#define DCLS_MAX 80
#define M_MAX (R_MAX*DCLS_MAX)     /* 81920 */
#define NIMG_MAX 4
#define NHEAD_MAX 408
#define LOG_MAX_CONST 4.1351665567423556f

/* ------------------ scratch (static device globals, no allocation) ------------------ */
__device__ __half g_x0h[(size_t)R_MAX*FEAT];
__device__ __half g_x0l[(size_t)R_MAX*FEAT];
__device__ __half g_W0th[(size_t)1024*FEAT];
__device__ __half g_W0tl[(size_t)1024*FEAT];
__device__ __half g_W1th[(size_t)1024*1024];
__device__ __half g_W1tl[(size_t)1024*1024];
__device__ __half g_Whth[(size_t)NHEAD_MAX*1024];
__device__ __half g_Whtl[(size_t)NHEAD_MAX*1024];
__device__ __half g_x1h[(size_t)R_MAX*1024];
__device__ __half g_x1l[(size_t)R_MAX*1024];
__device__ __half g_x2h[(size_t)R_MAX*1024];
__device__ __half g_x2l[(size_t)R_MAX*1024];
__device__ float  g_headout[(size_t)R_MAX*NHEAD_MAX];
__device__ float  g_bhead[NHEAD_MAX];
__device__ float  g_cscore[M_MAX];
__device__ float4 g_cbox[M_MAX];
__device__ float  g_score_c[(size_t)NIMG_MAX*M_MAX];
__device__ float4 g_box_c[(size_t)NIMG_MAX*M_MAX];
__device__ float  g_area_c[(size_t)NIMG_MAX*M_MAX];
__device__ int    g_cls_c[(size_t)NIMG_MAX*M_MAX];
__device__ int    g_cnt[NIMG_MAX];

/* ------------------ helpers --------------------------------------------------------- */
__device__ __forceinline__ uint32_t smem_u32(const void* p) {
    uint32_t a;
    asm("{ .reg .u64 t; cvta.to.shared.u64 t, %1; cvt.u32.u64 %0, t; }" : "=r"(a) : "l"(p));
    return a;
}
__device__ __forceinline__ void split_h(float v, __half& hi, __half& lo)
{
    hi = __float2half_rn(v);
    lo = __float2half_rn(v - __half2float(hi));
}

#define LDSM4(r0,r1,r2,r3, addr) \
    asm volatile("ldmatrix.sync.aligned.m8n8.x4.shared.b16 {%0,%1,%2,%3}, [%4];" \
        : "=r"(r0),"=r"(r1),"=r"(r2),"=r"(r3) : "r"(addr))

#define MMA16816(d, a, b) \
    asm volatile("mma.sync.aligned.m16n8k16.row.col.f32.f16.f16.f32 " \
        "{%0,%1,%2,%3}, {%4,%5,%6,%7}, {%8,%9}, {%0,%1,%2,%3};" \
        : "+f"((d)[0]), "+f"((d)[1]), "+f"((d)[2]), "+f"((d)[3]) \
        : "r"((a)[0]), "r"((a)[1]), "r"((a)[2]), "r"((a)[3]), "r"((b)[0]), "r"((b)[1]))

#define CPASYNC16(dst, src, sz) \
    asm volatile("cp.async.ca.shared.global [%0], [%1], 16, %2;" \
        :: "r"(dst), "l"(src), "r"(sz))

/* ------------------ ROI align: one block per proposal, 256 threads = channels ------- */
__global__ void roi_align_kernel(const float* __restrict__ prop,
                                 const int*   __restrict__ imidx,
                                 const float* __restrict__ f0, const float* __restrict__ f1,
                                 const float* __restrict__ f2, const float* __restrict__ f3,
                                 int H0, int H1, int H2, int H3)
{
    int r = blockIdx.x;
    __shared__ int   s_lvl, s_img, s_H;
    __shared__ int   s_y0[49], s_y1[49], s_x0[49], s_x1[49];
    __shared__ float s_wx[49], s_wy[49];

    if (threadIdx.x == 0) {
        float x1 = prop[r*4+0], y1 = prop[r*4+1], x2 = prop[r*4+2], y2 = prop[r*4+3];
        float pw = x2 - x1, ph = y2 - y1;
        float l = floorf(4.0f + log2f(sqrtf(pw*ph) / 224.0f + 1e-6f));
        l = fminf(fmaxf(l, 2.0f), 5.0f);
        int lvl = (int)l - 2;
        s_lvl = lvl;
        s_img = imidx[r];
        s_H   = (lvl==0 ? H0 : lvl==1 ? H1 : lvl==2 ? H2 : H3);
    }
    __syncthreads();
    int lvl = s_lvl, H = s_H;

    if (threadIdx.x < 49) {
        int py = threadIdx.x / 7, px = threadIdx.x % 7;
        float s  = 1.0f / (float)(4 << lvl);
        float x1 = prop[r*4+0]*s, y1 = prop[r*4+1]*s;
        float x2 = prop[r*4+2]*s, y2 = prop[r*4+3]*s;
        float gx = (px + 0.5f) / (float)POOL;
        float gy = (py + 0.5f) / (float)POOL;
        float xx = x1 + gx*(x2 - x1) - 0.5f;
        float yy = y1 + gy*(y2 - y1) - 0.5f;
        float x0f = floorf(xx), y0f = floorf(yy);
        s_wx[threadIdx.x] = xx - x0f;
        s_wy[threadIdx.x] = yy - y0f;
        int xi = (int)x0f, yi = (int)y0f;
        s_x0[threadIdx.x] = min(max(xi,     0), H-1);
        s_x1[threadIdx.x] = min(max(xi + 1, 0), H-1);
        s_y0[threadIdx.x] = min(max(yi,     0), H-1);
        s_y1[threadIdx.x] = min(max(yi + 1, 0), H-1);
    }
    __syncthreads();

    const float* fm = (lvl==0 ? f0 : lvl==1 ? f1 : lvl==2 ? f2 : f3);
    size_t imgBase = (size_t)s_img * H * H * C_CH;
    int c = threadIdx.x;
    size_t outBase = (size_t)r * FEAT;

    for (int b = 0; b < 49; b++) {
        float wx = s_wx[b], wy = s_wy[b];
        size_t row0 = imgBase + (size_t)s_y0[b] * H * C_CH;
        size_t row1 = imgBase + (size_t)s_y1[b] * H * C_CH;
        size_t cx0  = (size_t)s_x0[b] * C_CH + c;
        size_t cx1  = (size_t)s_x1[b] * C_CH + c;
        float v00 = fm[row0 + cx0];
        float v01 = fm[row0 + cx1];
        float v10 = fm[row1 + cx0];
        float v11 = fm[row1 + cx1];
        float v = v00*(1.f-wx)*(1.f-wy) + v01*wx*(1.f-wy)
                + v10*(1.f-wx)*wy       + v11*wx*wy;
        __half h, l; split_h(v, h, l);
        g_x0h[outBase + b*C_CH + c] = h;
        g_x0l[outBase + b*C_CH + c] = l;
    }
}

/* ------------------ transpose + fp16 split: in fp32 [K][N] -> out [roff+n][Kout] ---- */
__global__ void tsplit_kernel(const float* __restrict__ in, int K, int N,
                              __half* __restrict__ outH, __half* __restrict__ outL,
                              int roff, int Kout)
{
    __shared__ float tile[32][33];
    int k0 = blockIdx.y * 32, n0 = blockIdx.x * 32;
    int tx = threadIdx.x, ty = threadIdx.y;   /* (32, 8) */
    #pragma unroll
    for (int j = 0; j < 4; j++) {
        int k = k0 + ty + j*8, n = n0 + tx;
        tile[ty + j*8][tx] = (k < K && n < N) ? in[(size_t)k * N + n] : 0.f;
    }
    __syncthreads();
    #pragma unroll
    for (int j = 0; j < 4; j++) {
        int n = n0 + ty + j*8, k = k0 + tx;
        if (n < N && k < Kout) {
            __half h, l; split_h(tile[tx][ty + j*8], h, l);
            size_t o = (size_t)(roff + n) * Kout + k;
            outH[o] = h;
            outL[o] = l;
        }
    }
}

__global__ void pack_bias_kernel(const float* __restrict__ bc, const float* __restrict__ br,
                                 int NC, int NR)
{
    int t = threadIdx.x;
    if (t < NC + NR)
        g_bhead[t] = (t < NC) ? bc[t] : br[t - NC];
}

/* ------------------ fp16x2 tensor-core GEMM ----------------------------------------- */
/* C[M,N] = A[M,K] * Bt[N,K]^T + bias.  A,Bt pre-split hi/lo fp16, both K-major.        */
/* 3 HMMA passes: hh + hl + lh  (~2^-22 accuracy).                                      */
/* CTA tile 128x64, BK=32, 256 threads, 4-stage cp.async, 1 sync per k-tile.            */

#define SA 40
#define AH_B 0
#define AL_B 10240
#define BH_B 20480
#define BL_B 25600
#define GSTG 30720
#define GT_STAGES 4
#define GT_DSMEM (GT_STAGES*GSTG)

__global__ __launch_bounds__(256) void gemm_h2(
    const __half* __restrict__ Ah, const __half* __restrict__ Al,
    const __half* __restrict__ Bh, const __half* __restrict__ Bl,
    const float* __restrict__ bias,
    float* __restrict__ Cf, __half* __restrict__ Ch, __half* __restrict__ Cl,
    int M, int N, int K, int mode)
{
    extern __shared__ __align__(16) char sm[];
    uint32_t smb = smem_u32(sm);

    int tid = threadIdx.x, lane = tid & 31, warp = tid >> 5;
    int mBase = blockIdx.y * 128, nBase = blockIdx.x * 64;
    int wm = (warp & 3) * 32, wn = (warp >> 2) * 32;

    float acc[2][4][4];
    #pragma unroll
    for (int i = 0; i < 2; i++)
        #pragma unroll
        for (int j = 0; j < 4; j++)
            #pragma unroll
            for (int q = 0; q < 4; q++) acc[i][j][q] = 0.f;

    int tiles = K >> 5;

    auto loadTile = [&](int t) {
        if (t < tiles) {
            int kt = t << 5;
            uint32_t base = smb + (uint32_t)(t % GT_STAGES) * GSTG;
            #pragma unroll
            for (int i = 0; i < 2; i++) {
                int ch = tid + i*256;
                int row = ch >> 2, kc = (ch & 3) << 3;
                size_t gi = (size_t)(mBase + row) * K + kt + kc;
                uint32_t d = base + (uint32_t)(row*SA + kc)*2;
                int sz = (mBase + row < M) ? 16 : 0;
                CPASYNC16(d + AH_B, Ah + gi, sz);
                CPASYNC16(d + AL_B, Al + gi, sz);
            }
            {
                int row = tid >> 2, kc = (tid & 3) << 3;
                size_t gi = (size_t)(nBase + row) * K + kt + kc;
                uint32_t d = base + (uint32_t)(row*SA + kc)*2;
                int sz = (nBase + row < N) ? 16 : 0;
                CPASYNC16(d + BH_B, Bh + gi, sz);
                CPASYNC16(d + BL_B, Bl + gi, sz);
            }
        }
        asm volatile("cp.async.commit_group;");
    };

    loadTile(0); loadTile(1); loadTile(2);

    int lm = lane >> 3, lr = lane & 7;
    uint32_t aoff0 = (uint32_t)((wm + (lm&1)*8 + lr)*SA + (lm>>1)*8) * 2;
    uint32_t boff0 = (uint32_t)((wn + (lm>>1)*8 + lr)*SA + (lm&1)*8) * 2;

    for (int t = 0; t < tiles; t++) {
        asm volatile("cp.async.wait_group 2;");
        __syncthreads();
        uint32_t base = smb + (uint32_t)(t % GT_STAGES) * GSTG;

        #pragma unroll
        for (int ks = 0; ks < 2; ks++) {
            uint32_t kb = (uint32_t)(ks * 16) * 2;
            uint32_t ah[2][4], al[2][4];
            #pragma unroll
            for (int mi = 0; mi < 2; mi++) {
                uint32_t off = aoff0 + (uint32_t)(mi*16*SA)*2 + kb;
                LDSM4(ah[mi][0], ah[mi][1], ah[mi][2], ah[mi][3], base + AH_B + off);
                LDSM4(al[mi][0], al[mi][1], al[mi][2], al[mi][3], base + AL_B + off);
            }
            uint32_t bh[4][2], bl[4][2];
            #pragma unroll
            for (int g = 0; g < 2; g++) {
                uint32_t off = boff0 + (uint32_t)(g*16*SA)*2 + kb;
                uint32_t r0, r1, r2, r3;
                LDSM4(r0, r1, r2, r3, base + BH_B + off);
                bh[g*2][0]=r0; bh[g*2][1]=r1; bh[g*2+1][0]=r2; bh[g*2+1][1]=r3;
                LDSM4(r0, r1, r2, r3, base + BL_B + off);
                bl[g*2][0]=r0; bl[g*2][1]=r1; bl[g*2+1][0]=r2; bl[g*2+1][1]=r3;
            }
            #pragma unroll
            for (int mi = 0; mi < 2; mi++)
                #pragma unroll
                for (int nj = 0; nj < 4; nj++)
                    MMA16816(acc[mi][nj], ah[mi], bh[nj]);
            #pragma unroll
            for (int mi = 0; mi < 2; mi++)
                #pragma unroll
                for (int nj = 0; nj < 4; nj++)
                    MMA16816(acc[mi][nj], ah[mi], bl[nj]);
            #pragma unroll
            for (int mi = 0; mi < 2; mi++)
                #pragma unroll
                for (int nj = 0; nj < 4; nj++)
                    MMA16816(acc[mi][nj], al[mi], bh[nj]);
        }

        loadTile(t + 3);
    }

    /* epilogue */
    #pragma unroll
    for (int mi = 0; mi < 2; mi++) {
        #pragma unroll
        for (int nj = 0; nj < 4; nj++) {
            #pragma unroll
            for (int q = 0; q < 4; q++) {
                int row = mBase + wm + mi*16 + (lane >> 2) + (q >> 1)*8;
                int col = nBase + wn + nj*8 + ((lane & 3) << 1) + (q & 1);
                if (row < M && col < N) {
                    float v = acc[mi][nj][q] + bias[col];
                    if (mode == 1) {
                        v = fmaxf(v, 0.f);
                        __half h, l; split_h(v, h, l);
                        Ch[(size_t)row * N + col] = h;
                        Cl[(size_t)row * N + col] = l;
                    } else {
                        Cf[(size_t)row * N + col] = v;
                    }
                }
            }
        }
    }
}

/* ------------------ softmax + box decode: one block (128 thr) per proposal ---------- */
__global__ void decode_kernel(const float* __restrict__ prop,
                              const int*   __restrict__ imidx,
                              const float* __restrict__ imsizes,
                              const float* __restrict__ sthr_p,
                              const float* __restrict__ minsz_p,
                              int NC, int NT)
{
    int r = blockIdx.x;
    int t = threadIdx.x;
    __shared__ float sl[128];
    __shared__ float smax, ssum;

    const float* head = &g_headout[(size_t)r * NT];

    if (t < NC) sl[t] = head[t];
    __syncthreads();
    if (t == 0) { float m = sl[0]; for (int i = 1; i < NC; i++) m = fmaxf(m, sl[i]); smax = m; }
    __syncthreads();
    if (t < NC) sl[t] = expf(sl[t] - smax);
    __syncthreads();
    if (t == 0) { float s = 0.f; for (int i = 0; i < NC; i++) s += sl[i]; ssum = s; }
    __syncthreads();

    int D = NC - 1;
    if (t < D) {
        float score = sl[t+1] / ssum;
        float px1 = prop[r*4+0], py1 = prop[r*4+1];
        float px2 = prop[r*4+2], py2 = prop[r*4+3];
        float pw = px2 - px1, ph = py2 - py1;
        float cx = (px1 + px2)*0.5f, cy = (py1 + py2)*0.5f;
        const float* rg = &head[NC + (t+1)*4];
        float dx = rg[0]*0.1f, dy = rg[1]*0.1f;
        float dw = fminf(rg[2]*0.2f, LOG_MAX_CONST);
        float dh = fminf(rg[3]*0.2f, LOG_MAX_CONST);
        float ncx = dx*pw + cx, ncy = dy*ph + cy;
        float nw  = expf(dw)*pw, nh  = expf(dh)*ph;
        int im = imidx[r];
        float hb = imsizes[im*2+0], wb = imsizes[im*2+1];
        float bx1 = fminf(fmaxf(ncx - nw*0.5f, 0.f), wb);
        float bx2 = fminf(fmaxf(ncx + nw*0.5f, 0.f), wb);
        float by1 = fminf(fmaxf(ncy - nh*0.5f, 0.f), hb);
        float by2 = fminf(fmaxf(ncy + nh*0.5f, 0.f), hb);
        float sthr = *sthr_p, minsz = *minsz_p;
        bool valid = (score > sthr) && (bx2 - bx1 >= minsz) && (by2 - by1 >= minsz);
        int m = r*D + t;
        g_cscore[m] = valid ? score : -1.0f;
        g_cbox[m]   = make_float4(bx1, by1, bx2, by2);
    }
}

/* ------------------ deterministic per-image compaction (x4 vectorized) -------------- */
__global__ __launch_bounds__(1024) void compact_kernel(const int* __restrict__ imidx,
                                                       int M, int D)
{
    int img  = blockIdx.x;
    int tid  = threadIdx.x;
    int lane = tid & 31, wid = tid >> 5;
    __shared__ int warpSum[32], warpOff[32];
    __shared__ int sBase, sTot;
    if (tid == 0) sBase = 0;
    __syncthreads();

    const int VEC = 4, CHUNK = 1024 * VEC;
    for (int start = 0; start < M; start += CHUNK) {
        int cnt = 0; float sv[VEC]; int mi[VEC];
        int m0 = start + tid * VEC;
        #pragma unroll
        for (int j = 0; j < VEC; j++) {
            int m = m0 + j;
            if (m < M) {
                float v = g_cscore[m];
                if (v > 0.f && imidx[m / D] == img) { sv[cnt] = v; mi[cnt] = m; cnt++; }
            }
        }
        int pre = cnt;
        #pragma unroll
        for (int o = 1; o < 32; o <<= 1) {
            int x = __shfl_up_sync(0xffffffffu, pre, o);
            if (lane >= o) pre += x;
        }
        if (lane == 31) warpSum[wid] = pre;
        int excl = pre - cnt;
        __syncthreads();
        if (tid == 0) {
            int s = 0;
            for (int w = 0; w < 32; w++) { warpOff[w] = s; s += warpSum[w]; }
            sTot = s;
        }
        __syncthreads();
        int base0 = sBase + warpOff[wid] + excl;
        for (int q = 0; q < cnt; q++) {
            int m = mi[q];
            size_t o = (size_t)img*M_MAX + base0 + q;
            float4 b = g_cbox[m];
            g_score_c[o] = sv[q];
            g_box_c[o]   = b;
            g_area_c[o]  = (b.z - b.x)*(b.w - b.y);
            g_cls_c[o]   = (m % D) + 1;
        }
        __syncthreads();
        if (tid == 0) sBase += sTot;
        __syncthreads();
    }
    if (tid == 0) g_cnt[img] = sBase;
}

/* ------------------ sequential NMS: one block per image, smem scores ---------------- */
#define NMS_CAP 32768
#define NMS_T   512
__global__ __launch_bounds__(NMS_T) void nms_kernel(const float* __restrict__ iou_p,
                                                    float* __restrict__ out,
                                                    int n, int imtop)
{
    extern __shared__ float ssc[];
    int img = blockIdx.x, tid = threadIdx.x;
    int lane = tid & 31, warp = tid >> 5;
    int K = g_cnt[img];
    float iouT = *iou_p;
    float*  gsc = &g_score_c[(size_t)img*M_MAX];
    float4* bx  = &g_box_c[(size_t)img*M_MAX];
    float*  ar  = &g_area_c[(size_t)img*M_MAX];
    int*    cl  = &g_cls_c[(size_t)img*M_MAX];

    bool useS = (K <= NMS_CAP);
    float* sc = useS ? ssc : gsc;
    if (useS) for (int k = tid; k < K; k += NMS_T) ssc[k] = gsc[k];

    __shared__ unsigned long long wred[NMS_T/32];
    __shared__ float4 shb; __shared__ float sha; __shared__ int shc, shi; __shared__ float shv;
    __syncthreads();

    float* oB = out + (size_t)img*imtop*4;
    float* oS = out + (size_t)n*imtop*4 + (size_t)img*imtop;
    float* oC = out + (size_t)n*imtop*5 + (size_t)img*imtop;

    int t = 0;
    for (; t < imtop; t++) {
        /* packed (score, first-index) argmax: bits(score)<<32 | (MAX - idx) */
        unsigned long long best = 0ull;
        for (int k = tid; k < K; k += NMS_T) {
            float v = sc[k];
            if (v > 0.f) {
                unsigned long long p =
                    ((unsigned long long)__float_as_uint(v) << 32) |
                    (unsigned)(0x7FFFFFFF - k);
                if (p > best) best = p;
            }
        }
        #pragma unroll
        for (int o = 16; o; o >>= 1) {
            unsigned long long q = __shfl_xor_sync(0xffffffffu, best, o);
            if (q > best) best = q;
        }
        if (lane == 0) wred[warp] = best;
        __syncthreads();
        if (warp == 0) {
            unsigned long long b2 = (lane < NMS_T/32) ? wred[lane] : 0ull;
            #pragma unroll
            for (int o = 8; o; o >>= 1) {
                unsigned long long q = __shfl_xor_sync(0xffffffffu, b2, o);
                if (q > b2) b2 = q;
            }
            if (lane == 0) {
                if (b2) {
                    int wi = 0x7FFFFFFF - (int)(unsigned)(b2 & 0xFFFFFFFFu);
                    shv = __uint_as_float((unsigned)(b2 >> 32));
                    shi = wi; shb = bx[wi]; sha = ar[wi]; shc = cl[wi];
                } else {
                    shv = -1.f;
                }
            }
        }
        __syncthreads();
        float wv = shv;
        if (wv <= 0.f) break;
        int wi = shi; float4 wb = shb; float wa = sha; int wc = shc;
        for (int k = tid; k < K; k += NMS_T) {
            float v = sc[k];
            if (v <= 0.f) continue;
            if (k == wi) { sc[k] = -1.f; continue; }
            if (cl[k] != wc) continue;
            float4 b = bx[k];
            float iw = fmaxf(fminf(wb.z, b.z) - fmaxf(wb.x, b.x), 0.f);
            float ih = fmaxf(fminf(wb.w, b.w) - fmaxf(wb.y, b.y), 0.f);
            float inter = iw * ih;
            float iou = inter / (wa + ar[k] - inter + 1e-6f);
            if (iou > iouT) sc[k] = -1.f;
        }
        if (tid == 0) {
            oB[t*4+0] = wb.x; oB[t*4+1] = wb.y; oB[t*4+2] = wb.z; oB[t*4+3] = wb.w;
            oS[t] = wv;
            oC[t] = (float)wc;
        }
        __syncthreads();
    }
    /* fill the tail: once the max is <= 0 it stays <= 0 */
    for (int u = t + tid; u < imtop; u += NMS_T) {
        oB[u*4+0] = 0.f; oB[u*4+1] = 0.f; oB[u*4+2] = 0.f; oB[u*4+3] = 0.f;
        oS[u] = 0.f;
        oC[u] = -1.f;
    }
}

/* ------------------ host launch ---------------------------------------------------- */
extern "C" void kernel_launch(void* const* d_in, const int* in_sizes, int n_in,
                              void* d_out, int out_size)
{
    const float* prop    = (const float*)d_in[0];
    const int*   imidx   = (const int*)  d_in[1];
    const float* f0      = (const float*)d_in[2];
    const float* f1      = (const float*)d_in[3];
    const float* f2      = (const float*)d_in[4];
    const float* f3      = (const float*)d_in[5];
    const float* W0      = (const float*)d_in[6];
    const float* b0      = (const float*)d_in[7];
    const float* W1      = (const float*)d_in[8];
    const float* b1      = (const float*)d_in[9];
    const float* Wc      = (const float*)d_in[10];
    const float* bc      = (const float*)d_in[11];
    const float* Wr      = (const float*)d_in[12];
    const float* br      = (const float*)d_in[13];
    const float* imsizes = (const float*)d_in[14];
    const float* sthr    = (const float*)d_in[15];
    const float* iouthr  = (const float*)d_in[16];
    const float* minsz   = (const float*)d_in[18];

    int R  = in_sizes[0] / 4;
    int n  = in_sizes[14] / 2;
    int imtop = out_size / (6 * n);
    int N0 = in_sizes[7];
    int N1 = in_sizes[9];
    int NC = in_sizes[11];
    int NR = in_sizes[13];
    int NT = NC + NR;
    int D  = NC - 1;
    int M  = R * D;

    int H0 = (int)(sqrt((double)in_sizes[2] / ((double)n * C_CH)) + 0.5);
    int H1 = (int)(sqrt((double)in_sizes[3] / ((double)n * C_CH)) + 0.5);
    int H2 = (int)(sqrt((double)in_sizes[4] / ((double)n * C_CH)) + 0.5);
    int H3 = (int)(sqrt((double)in_sizes[5] / ((double)n * C_CH)) + 0.5);

    __half *px0h, *px0l, *pW0h, *pW0l, *pW1h, *pW1l, *pWhh, *pWhl;
    __half *px1h, *px1l, *px2h, *px2l;
    float *phead, *pbh;
    cudaGetSymbolAddress((void**)&px0h, g_x0h);  cudaGetSymbolAddress((void**)&px0l, g_x0l);
    cudaGetSymbolAddress((void**)&pW0h, g_W0th); cudaGetSymbolAddress((void**)&pW0l, g_W0tl);
    cudaGetSymbolAddress((void**)&pW1h, g_W1th); cudaGetSymbolAddress((void**)&pW1l, g_W1tl);
    cudaGetSymbolAddress((void**)&pWhh, g_Whth); cudaGetSymbolAddress((void**)&pWhl, g_Whtl);
    cudaGetSymbolAddress((void**)&px1h, g_x1h);  cudaGetSymbolAddress((void**)&px1l, g_x1l);
    cudaGetSymbolAddress((void**)&px2h, g_x2h);  cudaGetSymbolAddress((void**)&px2l, g_x2l);
    cudaGetSymbolAddress((void**)&phead, g_headout);
    cudaGetSymbolAddress((void**)&pbh,   g_bhead);

    cudaFuncSetAttribute(gemm_h2, cudaFuncAttributeMaxDynamicSharedMemorySize, GT_DSMEM);
    cudaFuncSetAttribute(nms_kernel, cudaFuncAttributeMaxDynamicSharedMemorySize, NMS_CAP*4);

    /* 1. ROI align -> split pooled features; weight transpose+split */
    roi_align_kernel<<<R, 256>>>(prop, imidx, f0, f1, f2, f3, H0, H1, H2, H3);
    {
        dim3 b(32, 8);
        tsplit_kernel<<<dim3((N0+31)/32, (FEAT+31)/32), b>>>(W0, FEAT, N0, pW0h, pW0l, 0, FEAT);
        tsplit_kernel<<<dim3((N1+31)/32, (N0+31)/32),  b>>>(W1, N0, N1, pW1h, pW1l, 0, N0);
        tsplit_kernel<<<dim3((NC+31)/32, (N1+31)/32),  b>>>(Wc, N1, NC, pWhh, pWhl, 0, N1);
        tsplit_kernel<<<dim3((NR+31)/32, (N1+31)/32),  b>>>(Wr, N1, NR, pWhh, pWhl, NC, N1);
        pack_bias_kernel<<<1, 512>>>(bc, br, NC, NR);
    }

    /* 2. FC1 (FEAT->N0) + ReLU, split fp16 out */
    {
        dim3 g((N0 + 63)/64, (R + 127)/128);
        gemm_h2<<<g, 256, GT_DSMEM>>>(px0h, px0l, pW0h, pW0l, b0,
                                      nullptr, px1h, px1l, R, N0, FEAT, 1);
    }
    /* 3. FC2 (N0->N1) + ReLU, split fp16 out */
    {
        dim3 g((N1 + 63)/64, (R + 127)/128);
        gemm_h2<<<g, 256, GT_DSMEM>>>(px1h, px1l, pW1h, pW1l, b1,
                                      nullptr, px2h, px2l, R, N1, N0, 1);
    }
    /* 4. fused class+reg head (N1->NT), fp32 out */
    {
        dim3 g((NT + 63)/64, (R + 127)/128);
        gemm_h2<<<g, 256, GT_DSMEM>>>(px2h, px2l, pWhh, pWhl, pbh,
                                      phead, nullptr, nullptr, R, NT, N1, 0);
    }
    /* 5. softmax + box decode */
    decode_kernel<<<R, 128>>>(prop, imidx, imsizes, sthr, minsz, NC, NT);

    /* 6. deterministic per-image compaction */
    compact_kernel<<<n, 1024>>>(imidx, M, D);

    /* 7. sequential NMS + output write */
    nms_kernel<<<n, NMS_T, NMS_CAP*4>>>(iouthr, (float*)d_out, n, imtop);
}